// round 2
// baseline (speedup 1.0000x reference)
#include <cuda_runtime.h>
#include <math.h>

#define NAg 8
#define Hdim 64
#define NNdim 128
#define AWdim 64
#define LATENT 512
#define NACT 14
#define INDIM 96
#define BSZ 4096
#define NROWS 32768   // BSZ*NAg

// ---------------- scratch (__device__ globals, allowed) ----------------
__device__ float g_uae[NROWS * 128];       // ae1 pre-BN
__device__ float g_ae_acc[2 * 128];        // sum, sumsq
__device__ float g_ae_sc[128], g_ae_sh[128];
__device__ float g_mean[NROWS * 512];
__device__ float g_var[NROWS * 512];
__device__ float g_aw[NROWS * 512];        // awareness
__device__ float g_L[NROWS * 128];
__device__ float g_R[NROWS * 128];
__device__ float g_in_acc[5 * 128];        // sumL, sumR, sqL, sqR, cross
__device__ float g_in_sc[128], g_in_sh[128];
__device__ float g_wqkv[64 * 384];
__device__ float g_att[NROWS * 512];

// ---------------- kernel 0: zero accumulators ----------------
__global__ void k_zero() {
    int i = threadIdx.x;
    if (i < 256) g_ae_acc[i] = 0.f;
    if (i < 640) g_in_acc[i] = 0.f;
}

// ---------------- kernel A: fused mlp1 + GRU ----------------
// 32 rows / block, 256 threads
__global__ void k_mlp1_gru(
    const float* __restrict__ in, const float* __restrict__ hin,
    const float* __restrict__ W1, const float* __restrict__ b1,
    const float* __restrict__ Wih, const float* __restrict__ bih,
    const float* __restrict__ Whh, const float* __restrict__ bhh,
    float* __restrict__ hout)
{
    __shared__ float sInT[96][33];
    __shared__ float sXT[64][33];
    __shared__ float sHT[64][33];
    int tid = threadIdx.x;
    int row0 = blockIdx.x * 32;

    for (int idx = tid; idx < 32 * 96; idx += 256) {
        int r = idx / 96, k = idx % 96;
        sInT[k][r] = in[(row0 + r) * 96 + k];
    }
    for (int idx = tid; idx < 32 * 64; idx += 256) {
        int r = idx / 64, k = idx % 64;
        sHT[k][r] = hin[(row0 + r) * 64 + k];
    }
    __syncthreads();

    // X = relu(in @ W1 + b1)
    {
        int c = tid & 63;
        int rg = tid >> 6;   // 0..3 -> rows rg*8..+7
        float acc[8];
#pragma unroll
        for (int i = 0; i < 8; i++) acc[i] = 0.f;
        for (int k = 0; k < 96; k++) {
            float w = W1[k * 64 + c];
#pragma unroll
            for (int i = 0; i < 8; i++) acc[i] += sInT[k][rg * 8 + i] * w;
        }
        float b = b1[c];
#pragma unroll
        for (int i = 0; i < 8; i++) {
            float v = acc[i] + b;
            sXT[c][rg * 8 + i] = v > 0.f ? v : 0.f;
        }
    }
    __syncthreads();

    // GRU gates
    {
        int j = tid & 63;
        int rg = tid >> 6;
        float axr[8], axz[8], axn[8], ahr[8], ahz[8], ahn[8];
#pragma unroll
        for (int i = 0; i < 8; i++) { axr[i]=axz[i]=axn[i]=ahr[i]=ahz[i]=ahn[i]=0.f; }
        for (int k = 0; k < 64; k++) {
            float wr = Wih[k * 192 + j], wz = Wih[k * 192 + 64 + j], wn = Wih[k * 192 + 128 + j];
            float vr = Whh[k * 192 + j], vz = Whh[k * 192 + 64 + j], vn = Whh[k * 192 + 128 + j];
#pragma unroll
            for (int i = 0; i < 8; i++) {
                float x = sXT[k][rg * 8 + i];
                float h = sHT[k][rg * 8 + i];
                axr[i] += x * wr; axz[i] += x * wz; axn[i] += x * wn;
                ahr[i] += h * vr; ahz[i] += h * vz; ahn[i] += h * vn;
            }
        }
        float br = bih[j], bz = bih[64 + j], bn_ = bih[128 + j];
        float cr = bhh[j], cz = bhh[64 + j], cn = bhh[128 + j];
#pragma unroll
        for (int i = 0; i < 8; i++) {
            int r = rg * 8 + i;
            float xr = axr[i] + br, xz = axz[i] + bz, xn = axn[i] + bn_;
            float hr = ahr[i] + cr, hz = ahz[i] + cz, hn = ahn[i] + cn;
            float rg_ = 1.f / (1.f + expf(-(xr + hr)));
            float zg  = 1.f / (1.f + expf(-(xz + hz)));
            float ng  = tanhf(xn + rg_ * hn);
            float hprev = sHT[j][r];
            hout[(row0 + r) * 64 + j] = (1.f - zg) * ng + zg * hprev;
        }
    }
}

// ---------------- kernel B: ae1 GEMM + column stats ----------------
__global__ void k_ae1(const float* __restrict__ hsrc,
                      const float* __restrict__ Wae1, const float* __restrict__ bae1)
{
    __shared__ float sHT[64][33];
    __shared__ float sred[256];
    int tid = threadIdx.x;
    int row0 = blockIdx.x * 32;
    for (int idx = tid; idx < 32 * 64; idx += 256) {
        int r = idx / 64, k = idx % 64;
        sHT[k][r] = hsrc[(row0 + r) * 64 + k];
    }
    __syncthreads();
    int c = tid & 127;
    int rg = tid >> 7;   // 0..1 -> rows rg*16..+15
    float acc[16];
#pragma unroll
    for (int i = 0; i < 16; i++) acc[i] = 0.f;
    for (int k = 0; k < 64; k++) {
        float w = Wae1[k * 128 + c];
#pragma unroll
        for (int i = 0; i < 16; i++) acc[i] += sHT[k][rg * 16 + i] * w;
    }
    float b = bae1[c];
    float s = 0.f, q = 0.f;
#pragma unroll
    for (int i = 0; i < 16; i++) {
        float u = acc[i] + b;
        g_uae[(row0 + rg * 16 + i) * 128 + c] = u;
        s += u; q += u * u;
    }
    sred[tid] = s; __syncthreads();
    if (tid < 128) atomicAdd(&g_ae_acc[tid], sred[tid] + sred[tid + 128]);
    __syncthreads();
    sred[tid] = q; __syncthreads();
    if (tid < 128) atomicAdd(&g_ae_acc[128 + tid], sred[tid] + sred[tid + 128]);
}

// ---------------- kernel C: finalize ae BN scale/shift ----------------
__global__ void k_ae_fin(const float* __restrict__ g, const float* __restrict__ be) {
    int c = threadIdx.x;
    float m = g_ae_acc[c] * (1.f / 32768.f);
    float var = g_ae_acc[128 + c] * (1.f / 32768.f) - m * m;
    float s = rsqrtf(var + 1e-5f) * g[c];
    g_ae_sc[c] = s;
    g_ae_sh[c] = be[c] - m * s;
}

// ---------------- kernel D: ae2 GEMM -> mean, var ----------------
__global__ void k_ae2(const float* __restrict__ Wae2, const float* __restrict__ bae2)
{
    __shared__ float sUT[128][33];
    int tid = threadIdx.x;
    int row0 = blockIdx.x * 32;
    for (int idx = tid; idx < 32 * 128; idx += 256) {
        int r = idx / 128, k = idx % 128;
        float u = g_uae[(row0 + r) * 128 + k];
        float v = u * g_ae_sc[k] + g_ae_sh[k];
        sUT[k][r] = v >= 0.f ? v : 0.01f * v;
    }
    __syncthreads();
    for (int pass = 0; pass < 4; pass++) {
        int c = pass * 256 + tid;
        float acc[32];
#pragma unroll
        for (int r = 0; r < 32; r++) acc[r] = 0.f;
        for (int k = 0; k < 128; k++) {
            float w = Wae2[k * 1024 + c];
#pragma unroll
            for (int r = 0; r < 32; r++) acc[r] += sUT[k][r] * w;
        }
        float b = bae2[c];
        if (c < 512) {
#pragma unroll
            for (int r = 0; r < 32; r++) g_mean[(row0 + r) * 512 + c] = acc[r] + b;
        } else {
            int cc = c - 512;
#pragma unroll
            for (int r = 0; r < 32; r++)
                g_var[(row0 + r) * 512 + cc] = fmaxf(expf(acc[r] + b), 0.002f);
        }
    }
}

// ---------------- kernel E: awareness = mean + sqrt(var)*noise ----------------
__global__ void k_aware(const float* __restrict__ noise) {
    int idx = blockIdx.x * 256 + threadIdx.x;
    g_aw[idx] = g_mean[idx] + sqrtf(g_var[idx]) * noise[idx];
}

// ---------------- kernel F: L/R GEMMs + column stats ----------------
__global__ void k_LR(const float* __restrict__ hsrc, const float* __restrict__ Win1)
{
    __shared__ float sHT[64][33];
    int tid = threadIdx.x;
    int row0 = blockIdx.x * 32;
    for (int idx = tid; idx < 32 * 64; idx += 256) {
        int r = idx / 64, k = idx % 64;
        sHT[k][r] = hsrc[(row0 + r) * 64 + k];
    }
    __syncthreads();
    int c = tid;           // 0..255 : 0..127 -> L, 128..255 -> R
    int cm = c & 127;
    float acc[32];
#pragma unroll
    for (int r = 0; r < 32; r++) acc[r] = 0.f;
    for (int k = 0; k < 64; k++) {
        float w = (c < 128) ? Win1[k * 128 + cm] : Win1[(64 + k) * 128 + cm];
#pragma unroll
        for (int r = 0; r < 32; r++) acc[r] += sHT[k][r] * w;
    }
    float* dst = (c < 128) ? g_L : g_R;
    float s = 0.f, q = 0.f;
#pragma unroll
    for (int r = 0; r < 32; r++) {
        float v = acc[r];
        dst[(row0 + r) * 128 + cm] = v;
        s += v; q += v * v;
    }
    atomicAdd(&g_in_acc[c], s);
    atomicAdd(&g_in_acc[256 + c], q);
}

// ---------------- kernel G: cross term sum_b SL[b,c]*SR[b,c] ----------------
__global__ void k_cross() {
    __shared__ float sred[256];
    int tid = threadIdx.x;
    int c = tid & 127;
    int bg = tid >> 7;        // 0..1, 16 b's each
    int b0 = blockIdx.x * 32;
    float cr = 0.f;
    for (int bb = bg * 16; bb < bg * 16 + 16; bb++) {
        int b = b0 + bb;
        float sl = 0.f, sr = 0.f;
#pragma unroll
        for (int i = 0; i < 8; i++) {
            sl += g_L[(b * 8 + i) * 128 + c];
            sr += g_R[(b * 8 + i) * 128 + c];
        }
        cr += sl * sr;
    }
    sred[tid] = cr; __syncthreads();
    if (tid < 128) atomicAdd(&g_in_acc[512 + tid], sred[tid] + sred[tid + 128]);
}

// ---------------- kernel H: finalize infer BN scale/shift ----------------
__global__ void k_in_fin(const float* __restrict__ bin1,
                         const float* __restrict__ g, const float* __restrict__ be)
{
    int c = threadIdx.x;
    float sl = g_in_acc[c], sr = g_in_acc[128 + c];
    float ql = g_in_acc[256 + c], qr = g_in_acc[384 + c];
    float cr = g_in_acc[512 + c];
    float beta = bin1[c];
    const float Nr = 262144.f;
    float mean = 8.f * (sl + sr) / Nr + beta;
    float e2 = (8.f * ql + 8.f * qr + 2.f * cr + 16.f * beta * (sl + sr)) / Nr + beta * beta;
    float var = e2 - mean * mean;
    float s = rsqrtf(var + 1e-5f) * g[c];
    g_in_sc[c] = s;
    g_in_sh[c] = be[c] + (beta - mean) * s;
}

// ---------------- kernel I: infer main GEMM + KLD (one block per b) ----------------
__global__ void k_infer(const float* __restrict__ Win2, const float* __restrict__ bin2,
                        float* __restrict__ kld_out)
{
    __shared__ float sL[8][128], sR[8][128], sU[8][128], sIP[8][128];
    __shared__ float sred[128];
    int b = blockIdx.x;
    int tid = threadIdx.x;   // 128
    for (int idx = tid; idx < 1024; idx += 128) {
        int j = idx >> 7;
        sL[j][tid] = g_L[(b * 8 + j) * 128 + tid];
        sR[j][tid] = g_R[(b * 8 + j) * 128 + tid];
    }
    float sc = g_in_sc[tid], sh = g_in_sh[tid];
    float bcol = bin2[tid];
    float kacc = 0.f;
    __syncthreads();
    for (int i = 0; i < 8; i++) {
#pragma unroll
        for (int j = 0; j < 8; j++) {
            float v = (sL[i][tid] + sR[j][tid]) * sc + sh;
            sU[j][tid] = v >= 0.f ? v : 0.01f * v;
        }
        __syncthreads();
        float acc[8];
#pragma unroll
        for (int j = 0; j < 8; j++) acc[j] = 0.f;
        for (int k = 0; k < 128; k++) {
            float w = Win2[k * 128 + tid];
#pragma unroll
            for (int j = 0; j < 8; j++) acc[j] += sU[j][k] * w;
        }
#pragma unroll
        for (int j = 0; j < 8; j++) sIP[j][tid] = acc[j] + bcol;
        __syncthreads();
        const float* mrow = g_mean + (size_t)(b * 8 + i) * 512;
        const float* vrow = g_var + (size_t)(b * 8 + i) * 512;
        for (int idx = tid; idx < 512; idx += 128) {
            int j = idx >> 6, d = idx & 63;
            float im = sIP[j][d];
            float iv = fmaxf(expf(sIP[j][64 + d]), 0.002f);
            float m0 = mrow[idx];
            float v0 = vrow[idx];
            float dm = m0 - im;
            kacc += 0.5f * (logf(iv) - logf(v0)) + 0.5f * (v0 + dm * dm) / iv - 0.5f;
        }
        __syncthreads();
    }
    sred[tid] = kacc; __syncthreads();
    for (int s = 64; s > 0; s >>= 1) {
        if (tid < s) sred[tid] += sred[tid + s];
        __syncthreads();
    }
    if (tid == 0) kld_out[b] = sred[0] * (1.f / 4096.f);
}

// ---------------- kernel J: pack w_q|w_k|w_v ----------------
__global__ void k_pack(const float* __restrict__ wq, const float* __restrict__ wk,
                       const float* __restrict__ wv)
{
    int idx = blockIdx.x * 256 + threadIdx.x;
    if (idx >= 64 * 384) return;
    int k = idx / 384, c = idx % 384;
    float v = (c < 128) ? wq[k * 128 + c] : (c < 256) ? wk[k * 128 + c - 128] : wv[k * 128 + c - 256];
    g_wqkv[idx] = v;
}

// ---------------- kernel K: fused MHA (2 attention batches / block) ----------------
__global__ void k_attn(const float* __restrict__ wfc,
                       const float* __restrict__ gln, const float* __restrict__ bln)
{
    __shared__ float sA[2][8][64];
    __shared__ float sQKV[2][8][384];
    __shared__ float sP[2][4][8][8];
    __shared__ float sO[2][8][128];
    __shared__ float sF[2][8][64];
    __shared__ float sMu[2][8], sRs[2][8];
    int tid = threadIdx.x;
    int sub = tid >> 7, t = tid & 127;
    int batch = blockIdx.x * 2 + sub;

    for (int idx = t; idx < 512; idx += 128)
        sA[sub][idx >> 6][idx & 63] = g_aw[(size_t)batch * 512 + idx];
    __syncthreads();

    // qkv projections
    for (int p = 0; p < 3; p++) {
        int c = p * 128 + t;
        float acc[8];
#pragma unroll
        for (int s = 0; s < 8; s++) acc[s] = 0.f;
        for (int k = 0; k < 64; k++) {
            float w = g_wqkv[k * 384 + c];
#pragma unroll
            for (int s = 0; s < 8; s++) acc[s] += sA[sub][s][k] * w;
        }
#pragma unroll
        for (int s = 0; s < 8; s++) sQKV[sub][s][c] = acc[s];
    }
    __syncthreads();

    // scores + softmax
    if (t < 32) {
        int h = t >> 3, s = t & 7;
        float scv[8];
        float mx = -1e30f;
#pragma unroll
        for (int u = 0; u < 8; u++) {
            float d = 0.f;
#pragma unroll
            for (int dd = 0; dd < 32; dd++)
                d += sQKV[sub][s][h * 32 + dd] * sQKV[sub][u][128 + h * 32 + dd];
            d *= 0.17677669529663687f;  // 1/sqrt(32)
            scv[u] = d;
            mx = fmaxf(mx, d);
        }
        float sum = 0.f;
#pragma unroll
        for (int u = 0; u < 8; u++) { scv[u] = expf(scv[u] - mx); sum += scv[u]; }
        float inv = 1.f / sum;
#pragma unroll
        for (int u = 0; u < 8; u++) sP[sub][h][s][u] = scv[u] * inv;
    }
    __syncthreads();

    // o = P @ V
    for (int idx = t; idx < 1024; idx += 128) {
        int s = idx >> 7, c = idx & 127, h = c >> 5;
        float a = 0.f;
#pragma unroll
        for (int u = 0; u < 8; u++) a += sP[sub][h][s][u] * sQKV[sub][u][256 + c];
        sO[sub][s][c] = a;
    }
    __syncthreads();

    // fc + residual
    {
        int c = t & 63, sg = t >> 6;  // rows sg*4..+3
        float acc[4];
#pragma unroll
        for (int i = 0; i < 4; i++) acc[i] = 0.f;
        for (int k = 0; k < 128; k++) {
            float w = wfc[k * 64 + c];
#pragma unroll
            for (int i = 0; i < 4; i++) acc[i] += sO[sub][sg * 4 + i][k] * w;
        }
#pragma unroll
        for (int i = 0; i < 4; i++) sF[sub][sg * 4 + i][c] = acc[i] + sA[sub][sg * 4 + i][c];
    }
    __syncthreads();

    // LayerNorm stats
    if (t < 8) {
        float m = 0.f;
#pragma unroll
        for (int c = 0; c < 64; c++) m += sF[sub][t][c];
        m *= (1.f / 64.f);
        float v = 0.f;
#pragma unroll
        for (int c = 0; c < 64; c++) { float d = sF[sub][t][c] - m; v += d * d; }
        v *= (1.f / 64.f);
        sMu[sub][t] = m;
        sRs[sub][t] = rsqrtf(v + 1e-6f);
    }
    __syncthreads();

    for (int idx = t; idx < 512; idx += 128) {
        int s = idx >> 6, c = idx & 63;
        g_att[(size_t)batch * 512 + idx] =
            (sF[sub][s][c] - sMu[sub][s]) * sRs[sub][s] * gln[c] + bln[c];
    }
}

// ---------------- kernel L: mlp2 (q_vals) ----------------
__global__ void k_mlp2(const float* __restrict__ hsrc,
                       const float* __restrict__ W2, const float* __restrict__ b2,
                       float* __restrict__ qout)
{
    __shared__ float sWt[14 * 576];
    int tid = threadIdx.x;
    for (int idx = tid; idx < 14 * 576; idx += 256) {
        int c = idx / 576, k = idx % 576;
        sWt[c * 576 + k] = W2[k * 14 + c];
    }
    __syncthreads();
    int w = tid >> 5, l = tid & 31;
    int row = blockIdx.x * 8 + w;
    const float* hr = hsrc + (size_t)row * 64;
    const float* ar = g_att + (size_t)row * 512;
    float acc[14];
#pragma unroll
    for (int c = 0; c < 14; c++) acc[c] = 0.f;
    for (int k = l; k < 576; k += 32) {
        float v = (k < 64) ? hr[k] : ar[k - 64];
#pragma unroll
        for (int c = 0; c < 14; c++) acc[c] += v * sWt[c * 576 + k];
    }
#pragma unroll
    for (int c = 0; c < 14; c++) {
        float a = acc[c];
        for (int o = 16; o > 0; o >>= 1) a += __shfl_down_sync(0xffffffffu, a, o);
        if (l == 0) qout[(size_t)row * 14 + c] = a + b2[c];
    }
}

// ---------------- launch ----------------
extern "C" void kernel_launch(void* const* d_in, const int* in_sizes, int n_in,
                              void* d_out, int out_size)
{
    const float* inputs = (const float*)d_in[0];
    const float* hidden = (const float*)d_in[1];
    const float* noise  = (const float*)d_in[2];
    const float* w_mlp1 = (const float*)d_in[3];
    const float* b_mlp1 = (const float*)d_in[4];
    const float* w_ih   = (const float*)d_in[5];
    const float* b_ih   = (const float*)d_in[6];
    const float* w_hh   = (const float*)d_in[7];
    const float* b_hh   = (const float*)d_in[8];
    const float* w_ae1  = (const float*)d_in[9];
    const float* b_ae1  = (const float*)d_in[10];
    const float* g_ae   = (const float*)d_in[11];
    const float* be_ae  = (const float*)d_in[12];
    const float* w_ae2  = (const float*)d_in[13];
    const float* b_ae2  = (const float*)d_in[14];
    const float* w_in1  = (const float*)d_in[15];
    const float* b_in1  = (const float*)d_in[16];
    const float* g_in   = (const float*)d_in[17];
    const float* be_in  = (const float*)d_in[18];
    const float* w_in2  = (const float*)d_in[19];
    const float* b_in2  = (const float*)d_in[20];
    const float* w_q    = (const float*)d_in[21];
    const float* w_k    = (const float*)d_in[22];
    const float* w_v    = (const float*)d_in[23];
    const float* w_fc   = (const float*)d_in[24];
    const float* g_ln   = (const float*)d_in[25];
    const float* b_ln   = (const float*)d_in[26];
    const float* w_mlp2 = (const float*)d_in[27];
    const float* b_mlp2 = (const float*)d_in[28];

    float* out = (float*)d_out;
    float* q_out   = out;                         // 32768*14
    float* h_out   = out + NROWS * NACT;          // 32768*64
    float* kld_out = h_out + NROWS * Hdim;        // 4096

    k_zero<<<1, 640>>>();
    k_mlp1_gru<<<NROWS / 32, 256>>>(inputs, hidden, w_mlp1, b_mlp1, w_ih, b_ih, w_hh, b_hh, h_out);
    k_ae1<<<NROWS / 32, 256>>>(h_out, w_ae1, b_ae1);
    k_ae_fin<<<1, 128>>>(g_ae, be_ae);
    k_ae2<<<NROWS / 32, 256>>>(w_ae2, b_ae2);
    k_aware<<<(NROWS * 512) / 256, 256>>>(noise);
    k_LR<<<NROWS / 32, 256>>>(h_out, w_in1);
    k_cross<<<BSZ / 32, 256>>>();
    k_in_fin<<<1, 128>>>(b_in1, g_in, be_in);
    k_infer<<<BSZ, 128>>>(w_in2, b_in2, kld_out);
    k_pack<<<(64 * 384 + 255) / 256, 256>>>(w_q, w_k, w_v);
    k_attn<<<NROWS / 2, 256>>>(w_fc, g_ln, b_ln);
    k_mlp2<<<NROWS / 8, 256>>>(h_out, w_mlp2, b_mlp2, q_out);
}